// round 6
// baseline (speedup 1.0000x reference)
#include <cuda_runtime.h>
#include <math.h>
#include <float.h>

#define N_CAND 200000
#define DTXT 768
#define DIMG 1024
#define DC 256
#define KSEL 10
#define SIM_BLOCKS 148
#define TB 8

// ---- device scratch (no allocations allowed) ----
__device__ float g_cv[SIM_BLOCKS * KSEL];
__device__ int   g_ci[SIM_BLOCKS * KSEL];
__device__ int   g_idx[KSEL];
__device__ float g_z[21 * DC];
__device__ float g_feats[21 * DC];
__device__ float g_qkv[23 * DC];
__device__ float g_out1[DC];
__device__ float g_h1[4 * DC];
__device__ float g_f[DC];
__device__ float g_dummy;

#define CLUSTER_SYNC() do { __threadfence(); \
    asm volatile("barrier.cluster.arrive.aligned;" ::: "memory"); \
    asm volatile("barrier.cluster.wait.aligned;" ::: "memory"); \
} while (0)

// ============================================================
// 1) cosine-sim scan + fused per-block top-10 (smem lists)
//    148 blocks x 1024 threads, single wave, __ldcs streaming
// ============================================================
__global__ void __launch_bounds__(1024, 1) sim_kernel(const float* __restrict__ query,
                                                      const float* __restrict__ cand) {
    __shared__ float4 qs[DTXT / 4];
    __shared__ float wtv[32 * KSEL];
    __shared__ int   wti[32 * KSEL];
    int t = threadIdx.x, lane = t & 31, wid = t >> 5;

    for (int i = t; i < DTXT / 4; i += 1024) qs[i] = reinterpret_cast<const float4*>(query)[i];
    for (int i = t; i < 32 * KSEL; i += 1024) { wtv[i] = -FLT_MAX; wti[i] = -1; }
    __syncthreads();

    int gw = blockIdx.x * 32 + wid;
    int nw = gridDim.x * 32;
    float th = -FLT_MAX;

    for (int row = gw; row < N_CAND; row += nw) {
        const float4* rp = reinterpret_cast<const float4*>(cand + (size_t)row * DTXT);
        float4 c[6];
#pragma unroll
        for (int i = 0; i < 6; i++) c[i] = __ldcs(&rp[i * 32 + lane]);
        float dot = 0.f, ss = 0.f;
#pragma unroll
        for (int i = 0; i < 6; i++) {
            float4 q = qs[i * 32 + lane];
            dot += c[i].x * q.x + c[i].y * q.y + c[i].z * q.z + c[i].w * q.w;
            ss  += c[i].x * c[i].x + c[i].y * c[i].y + c[i].z * c[i].z + c[i].w * c[i].w;
        }
#pragma unroll
        for (int o = 16; o; o >>= 1) {
            dot += __shfl_xor_sync(0xffffffffu, dot, o);
            ss  += __shfl_xor_sync(0xffffffffu, ss,  o);
        }
        if (lane == 0) {
            float s = dot / fmaxf(sqrtf(ss), 1e-12f);
            if (s > th) {
                float* tv = &wtv[wid * KSEL]; int* ti = &wti[wid * KSEL];
                int pos = 0;
#pragma unroll
                for (int j = 0; j < KSEL; j++) pos += (tv[j] >= s) ? 1 : 0;
                for (int j = KSEL - 2; j >= pos; j--) { tv[j + 1] = tv[j]; ti[j + 1] = ti[j]; }
                tv[pos] = s; ti[pos] = row;
                th = tv[KSEL - 1];
            }
        }
    }
    __syncthreads();

    // warp 0: merge 32 sorted lists -> block top-10
    if (wid == 0) {
        int ptr = 0;
        for (int s = 0; s < KSEL; s++) {
            float v = (ptr < KSEL) ? wtv[lane * KSEL + ptr] : -FLT_MAX;
            float bv = v; int bl = lane;
#pragma unroll
            for (int o = 16; o; o >>= 1) {
                float ov = __shfl_xor_sync(0xffffffffu, bv, o);
                int   ol = __shfl_xor_sync(0xffffffffu, bl, o);
                if (ov > bv) { bv = ov; bl = ol; }
            }
            if (lane == bl) {
                g_cv[blockIdx.x * KSEL + s] = v;
                g_ci[blockIdx.x * KSEL + s] = wti[lane * KSEL + ptr];
                ptr++;
            }
        }
    }
}

// ============================================================
// 2) everything else: ONE kernel, 8-CTA cluster, HW barriers
// ============================================================
__global__ void __launch_bounds__(1024, 1) __cluster_dims__(TB, 1, 1) tail_kernel(
    const float* __restrict__ query,
    const float* __restrict__ cand_text,
    const float* __restrict__ cand_img,
    const float* __restrict__ proto,
    const float* __restrict__ W_txt, const float* __restrict__ b_txt,
    const float* __restrict__ g_txt, const float* __restrict__ be_txt,
    const float* __restrict__ W_img, const float* __restrict__ b_img,
    const float* __restrict__ g_img, const float* __restrict__ be_img,
    const float* __restrict__ Wq, const float* __restrict__ bq,
    const float* __restrict__ Wk, const float* __restrict__ bk,
    const float* __restrict__ Wv, const float* __restrict__ bv,
    const float* __restrict__ Wo, const float* __restrict__ bo,
    const float* __restrict__ g1, const float* __restrict__ be1,
    const float* __restrict__ W1, const float* __restrict__ b1,
    const float* __restrict__ W2, const float* __restrict__ b2,
    const float* __restrict__ g2, const float* __restrict__ be2,
    float* __restrict__ out) {

    __shared__ __align__(16) float sh[11264];   // 44 KB, aliased per phase
    int t = threadIdx.x, b = blockIdx.x;
    int lane = t & 31, w = t >> 5;

    // -------- Phase B: block 0 reduces 1480 candidates -> g_idx --------
    if (b == 0) {
        float* srv = sh;
        int*   sri = (int*)(sh + 32);
        int*   swin = (int*)(sh + 64);
        const int NC = SIM_BLOCKS * KSEL;
        float v0 = (t < NC) ? g_cv[t] : -FLT_MAX;
        int  id0 = (t < NC) ? g_ci[t] : -1;
        float v1 = (t + 1024 < NC) ? g_cv[t + 1024] : -FLT_MAX;
        int  id1 = (t + 1024 < NC) ? g_ci[t + 1024] : -1;

        for (int s = 0; s < KSEL; s++) {
            float lv = v0; int ls = 0;
            if (v1 > lv) { lv = v1; ls = 1; }
            float bv = lv; int bl = lane;
#pragma unroll
            for (int o = 16; o; o >>= 1) {
                float ov = __shfl_xor_sync(0xffffffffu, bv, o);
                int   ol = __shfl_xor_sync(0xffffffffu, bl, o);
                if (ov > bv) { bv = ov; bl = ol; }
            }
            if (lane == 0) { srv[w] = bv; sri[w] = bl; }
            __syncthreads();
            if (w == 0) {
                float wv = srv[lane]; int bw = lane;
#pragma unroll
                for (int o = 16; o; o >>= 1) {
                    float ov = __shfl_xor_sync(0xffffffffu, wv, o);
                    int   ow = __shfl_xor_sync(0xffffffffu, bw, o);
                    if (ov > wv) { wv = ov; bw = ow; }
                }
                if (lane == 0) swin[0] = (bw << 5) | sri[bw];
            }
            __syncthreads();
            int win = swin[0];
            if (w == (win >> 5) && lane == (win & 31)) {
                if (ls) { g_idx[s] = id1; v1 = -FLT_MAX; }
                else    { g_idx[s] = id0; v0 = -FLT_MAX; }
            }
            __syncthreads();
        }
    }
    CLUSTER_SYNC();

    // -------- Phase C1: batched projections -> g_z --------
    {
        int* sidx = (int*)(sh + 10304);
        if (t < KSEL) sidx[t] = g_idx[t];
        __syncthreads();
        float* xs = sh + 64;

        // text rows 0..10 (row0 = query)
        for (int i = t; i < 11 * DTXT; i += 1024) {
            int r = i / DTXT, cc = i - r * DTXT;
            xs[i] = (r == 0) ? __ldg(&query[cc])
                             : __ldg(&cand_text[(size_t)sidx[r - 1] * DTXT + cc]);
        }
        __syncthreads();
        {
            int c = b * 32 + w;
            const float4* w4 = reinterpret_cast<const float4*>(W_txt + (size_t)c * DTXT);
            const float4* x4 = reinterpret_cast<const float4*>(xs);
            float acc[11];
#pragma unroll
            for (int n = 0; n < 11; n++) acc[n] = 0.f;
#pragma unroll
            for (int i = 0; i < 6; i++) {
                float4 wv = __ldg(&w4[i * 32 + lane]);
#pragma unroll
                for (int n = 0; n < 11; n++) {
                    float4 a = x4[n * (DTXT / 4) + i * 32 + lane];
                    acc[n] += a.x * wv.x + a.y * wv.y + a.z * wv.z + a.w * wv.w;
                }
            }
#pragma unroll
            for (int n = 0; n < 11; n++) {
#pragma unroll
                for (int o = 16; o; o >>= 1) acc[n] += __shfl_xor_sync(0xffffffffu, acc[n], o);
            }
            if (lane == 0) {
                float bb = b_txt[c];
#pragma unroll
                for (int n = 0; n < 11; n++) g_z[n * DC + c] = acc[n] + bb;
            }
        }
        __syncthreads();

        // img rows 0..9
        for (int i = t; i < 10 * DIMG; i += 1024) {
            int r = i / DIMG, cc = i - r * DIMG;
            xs[i] = __ldg(&cand_img[(size_t)sidx[r] * DIMG + cc]);
        }
        __syncthreads();
        {
            int c = b * 32 + w;
            const float4* w4 = reinterpret_cast<const float4*>(W_img + (size_t)c * DIMG);
            const float4* x4 = reinterpret_cast<const float4*>(xs);
            float acc[10];
#pragma unroll
            for (int n = 0; n < 10; n++) acc[n] = 0.f;
#pragma unroll
            for (int i = 0; i < 8; i++) {
                float4 wv = __ldg(&w4[i * 32 + lane]);
#pragma unroll
                for (int n = 0; n < 10; n++) {
                    float4 a = x4[n * (DIMG / 4) + i * 32 + lane];
                    acc[n] += a.x * wv.x + a.y * wv.y + a.z * wv.z + a.w * wv.w;
                }
            }
#pragma unroll
            for (int n = 0; n < 10; n++) {
#pragma unroll
                for (int o = 16; o; o >>= 1) acc[n] += __shfl_xor_sync(0xffffffffu, acc[n], o);
            }
            if (lane == 0) {
                float bb = b_img[c];
#pragma unroll
                for (int n = 0; n < 10; n++) g_z[(11 + n) * DC + c] = acc[n] + bb;
            }
        }
    }
    CLUSTER_SYNC();

    // -------- Phase C2: LN + ReLU, warp-per-row (no block syncs) --------
    {
        int r = b + 8 * w;   // w<3 -> rows b, b+8, b+16
        if (w < 3 && r < 21) {
            float e[8];
#pragma unroll
            for (int j = 0; j < 8; j++) e[j] = g_z[r * DC + lane + 32 * j];
            float sm = 0.f;
#pragma unroll
            for (int j = 0; j < 8; j++) sm += e[j];
#pragma unroll
            for (int o = 16; o; o >>= 1) sm += __shfl_xor_sync(0xffffffffu, sm, o);
            float m = sm * (1.f / 256.f);
            float vv = 0.f;
#pragma unroll
            for (int j = 0; j < 8; j++) { float d = e[j] - m; vv += d * d; }
#pragma unroll
            for (int o = 16; o; o >>= 1) vv += __shfl_xor_sync(0xffffffffu, vv, o);
            float rstd = rsqrtf(vv * (1.f / 256.f) + 1e-5f);
            const float* gg = (r < 11) ? g_txt : g_img;
            const float* be = (r < 11) ? be_txt : be_img;
#pragma unroll
            for (int j = 0; j < 8; j++) {
                int cc = lane + 32 * j;
                float y = (e[j] - m) * rstd * __ldg(&gg[cc]) + __ldg(&be[cc]);
                g_feats[r * DC + cc] = fmaxf(y, 0.f);
            }
        }
    }
    CLUSTER_SYNC();

    // -------- Phase D: batched QKV -> g_qkv --------
    {
        float* sq = sh;            // 256
        float* sK = sh + 256;      // 2816
        float* sV = sh + 3072;     // 2816
        for (int i = t; i < DC; i += 1024) sq[i] = g_feats[i];
        for (int i = t; i < 11 * DC; i += 1024) {
            int r = i >> 8, cc = i & 255;
            sK[i] = (r == 0) ? __ldg(&proto[cc]) : g_feats[r * DC + cc];
            sV[i] = (r == 0) ? __ldg(&proto[cc]) : g_feats[(10 + r) * DC + cc];
        }
        __syncthreads();

        int c = b * 32 + w;
        {   // q projection (1 row)
            const float4* w4 = reinterpret_cast<const float4*>(Wq + (size_t)c * DC);
            const float4* x4 = reinterpret_cast<const float4*>(sq);
            float acc = 0.f;
#pragma unroll
            for (int i = 0; i < 2; i++) {
                float4 wv = __ldg(&w4[i * 32 + lane]);
                float4 a = x4[i * 32 + lane];
                acc += a.x * wv.x + a.y * wv.y + a.z * wv.z + a.w * wv.w;
            }
#pragma unroll
            for (int o = 16; o; o >>= 1) acc += __shfl_xor_sync(0xffffffffu, acc, o);
            if (lane == 0) g_qkv[c] = acc + bq[c];
        }
        {   // k projection (11 rows)
            const float4* w4 = reinterpret_cast<const float4*>(Wk + (size_t)c * DC);
            const float4* x4 = reinterpret_cast<const float4*>(sK);
            float acc[11];
#pragma unroll
            for (int n = 0; n < 11; n++) acc[n] = 0.f;
#pragma unroll
            for (int i = 0; i < 2; i++) {
                float4 wv = __ldg(&w4[i * 32 + lane]);
#pragma unroll
                for (int n = 0; n < 11; n++) {
                    float4 a = x4[n * 64 + i * 32 + lane];
                    acc[n] += a.x * wv.x + a.y * wv.y + a.z * wv.z + a.w * wv.w;
                }
            }
#pragma unroll
            for (int n = 0; n < 11; n++) {
#pragma unroll
                for (int o = 16; o; o >>= 1) acc[n] += __shfl_xor_sync(0xffffffffu, acc[n], o);
            }
            if (lane == 0) {
                float bb = bk[c];
#pragma unroll
                for (int n = 0; n < 11; n++) g_qkv[(1 + n) * DC + c] = acc[n] + bb;
            }
        }
        {   // v projection (11 rows)
            const float4* w4 = reinterpret_cast<const float4*>(Wv + (size_t)c * DC);
            const float4* x4 = reinterpret_cast<const float4*>(sV);
            float acc[11];
#pragma unroll
            for (int n = 0; n < 11; n++) acc[n] = 0.f;
#pragma unroll
            for (int i = 0; i < 2; i++) {
                float4 wv = __ldg(&w4[i * 32 + lane]);
#pragma unroll
                for (int n = 0; n < 11; n++) {
                    float4 a = x4[n * 64 + i * 32 + lane];
                    acc[n] += a.x * wv.x + a.y * wv.y + a.z * wv.z + a.w * wv.w;
                }
            }
#pragma unroll
            for (int n = 0; n < 11; n++) {
#pragma unroll
                for (int o = 16; o; o >>= 1) acc[n] += __shfl_xor_sync(0xffffffffu, acc[n], o);
            }
            if (lane == 0) {
                float bb = bv[c];
#pragma unroll
                for (int n = 0; n < 11; n++) g_qkv[(12 + n) * DC + c] = acc[n] + bb;
            }
        }
    }
    CLUSTER_SYNC();

    // -------- Phase E: attention + Wo + LN1 (block 0); others prefetch W1/W2 --------
    if (b == 0) {
        float* qp  = sh;
        float* kp  = sh + 256;
        float* vp  = sh + 3072;
        float* at  = sh + 5888;
        float* ctx = sh + 5936;
        float* sy  = sh + 6192;
        for (int i = t; i < DC; i += 1024) qp[i] = g_qkv[i];
        for (int i = t; i < 11 * DC; i += 1024) {
            kp[i] = g_qkv[DC + i];
            vp[i] = g_qkv[12 * DC + i];
        }
        __syncthreads();
        if (t < 44) {
            int h = t / 11, n = t % 11;
            float s = 0.f;
#pragma unroll
            for (int d = 0; d < 64; d++) s += qp[h * 64 + d] * kp[n * DC + h * 64 + d];
            at[t] = s * 0.125f;
        }
        __syncthreads();
        if (t < 4) {
            float mx = -FLT_MAX;
            for (int n = 0; n < 11; n++) mx = fmaxf(mx, at[t * 11 + n]);
            float sm = 0.f;
            for (int n = 0; n < 11; n++) { float e = expf(at[t * 11 + n] - mx); at[t * 11 + n] = e; sm += e; }
            float inv = 1.f / sm;
            for (int n = 0; n < 11; n++) at[t * 11 + n] *= inv;
        }
        __syncthreads();
        if (t < DC) {
            int h = t >> 6;
            float s = 0.f;
            for (int n = 0; n < 11; n++) s += at[h * 11 + n] * vp[n * DC + t];
            ctx[t] = s;
        }
        __syncthreads();
        const float4* c4 = reinterpret_cast<const float4*>(ctx);
#pragma unroll
        for (int j = 0; j < 8; j++) {
            int c = w * 8 + j;
            const float4* w4 = reinterpret_cast<const float4*>(Wo + (size_t)c * DC);
            float acc = 0.f;
#pragma unroll
            for (int i = 0; i < 2; i++) {
                float4 a = c4[i * 32 + lane];
                float4 wv = __ldg(&w4[i * 32 + lane]);
                acc += a.x * wv.x + a.y * wv.y + a.z * wv.z + a.w * wv.w;
            }
#pragma unroll
            for (int o = 16; o; o >>= 1) acc += __shfl_xor_sync(0xffffffffu, acc, o);
            if (lane == 0) sy[c] = acc + bo[c] + __ldg(&proto[c]);
        }
        __syncthreads();
        if (w == 0) {
            float e[8];
#pragma unroll
            for (int j = 0; j < 8; j++) e[j] = sy[lane + 32 * j];
            float sm = 0.f;
#pragma unroll
            for (int j = 0; j < 8; j++) sm += e[j];
#pragma unroll
            for (int o = 16; o; o >>= 1) sm += __shfl_xor_sync(0xffffffffu, sm, o);
            float m = sm * (1.f / 256.f);
            float vv = 0.f;
#pragma unroll
            for (int j = 0; j < 8; j++) { float d = e[j] - m; vv += d * d; }
#pragma unroll
            for (int o = 16; o; o >>= 1) vv += __shfl_xor_sync(0xffffffffu, vv, o);
            float rstd = rsqrtf(vv * (1.f / 256.f) + 1e-5f);
#pragma unroll
            for (int j = 0; j < 8; j++) {
                int cc = lane + 32 * j;
                g_out1[cc] = (e[j] - m) * rstd * __ldg(&g1[cc]) + __ldg(&be1[cc]);
            }
        }
    } else {
        // warm L2 with W1 + W2 while block 0 does attention
        const float4* p1 = reinterpret_cast<const float4*>(W1);
        const float4* p2 = reinterpret_cast<const float4*>(W2);
        float a = 0.f;
        for (int i = (b - 1) * 1024 + t; i < 65536; i += 7 * 1024) {
            float4 v = __ldg(&p1[i]); a += v.x + v.y + v.z + v.w;
        }
        for (int i = (b - 1) * 1024 + t; i < 65536; i += 7 * 1024) {
            float4 v = __ldg(&p2[i]); a += v.x + v.y + v.z + v.w;
        }
        if (a == 1.0e38f) g_dummy = a;
    }
    CLUSTER_SYNC();

    // -------- Phase F: FFN1 (1024 outputs over 256 warps x 4) --------
    {
        float* xs1 = sh;
        if (t < DC) xs1[t] = g_out1[t];
        __syncthreads();
        const float4* x4 = reinterpret_cast<const float4*>(xs1);
#pragma unroll
        for (int j = 0; j < 4; j++) {
            int c = (b * 32 + w) + 256 * j;
            const float4* w4 = reinterpret_cast<const float4*>(W1 + (size_t)c * DC);
            float acc = 0.f;
#pragma unroll
            for (int i = 0; i < 2; i++) {
                float4 a = x4[i * 32 + lane];
                float4 wv = __ldg(&w4[i * 32 + lane]);
                acc += a.x * wv.x + a.y * wv.y + a.z * wv.z + a.w * wv.w;
            }
#pragma unroll
            for (int o = 16; o; o >>= 1) acc += __shfl_xor_sync(0xffffffffu, acc, o);
            if (lane == 0) g_h1[c] = fmaxf(acc + b1[c], 0.f);
        }
    }
    CLUSTER_SYNC();

    // -------- Phase G: FFN2 (256 outputs, warp each, dot-1024) --------
    {
        float* xh = sh;
        xh[t] = g_h1[t];
        __syncthreads();
        int c = b * 32 + w;
        const float4* x4 = reinterpret_cast<const float4*>(xh);
        const float4* w4 = reinterpret_cast<const float4*>(W2 + (size_t)c * (4 * DC));
        float acc = 0.f;
#pragma unroll
        for (int i = 0; i < 8; i++) {
            float4 a = x4[i * 32 + lane];
            float4 wv = __ldg(&w4[i * 32 + lane]);
            acc += a.x * wv.x + a.y * wv.y + a.z * wv.z + a.w * wv.w;
        }
#pragma unroll
        for (int o = 16; o; o >>= 1) acc += __shfl_xor_sync(0xffffffffu, acc, o);
        if (lane == 0) g_f[c] = acc + b2[c];
    }
    CLUSTER_SYNC();

    // -------- Phase H: residual + LN2 + proto -> out (block 0 warp 0) --------
    if (b == 0 && w == 0) {
        float e[8];
#pragma unroll
        for (int j = 0; j < 8; j++) {
            int cc = lane + 32 * j;
            e[j] = g_f[cc] + g_out1[cc];
        }
        float sm = 0.f;
#pragma unroll
        for (int j = 0; j < 8; j++) sm += e[j];
#pragma unroll
        for (int o = 16; o; o >>= 1) sm += __shfl_xor_sync(0xffffffffu, sm, o);
        float m = sm * (1.f / 256.f);
        float vv = 0.f;
#pragma unroll
        for (int j = 0; j < 8; j++) { float d = e[j] - m; vv += d * d; }
#pragma unroll
        for (int o = 16; o; o >>= 1) vv += __shfl_xor_sync(0xffffffffu, vv, o);
        float rstd = rsqrtf(vv * (1.f / 256.f) + 1e-5f);
#pragma unroll
        for (int j = 0; j < 8; j++) {
            int cc = lane + 32 * j;
            out[cc] = (e[j] - m) * rstd * __ldg(&g2[cc]) + __ldg(&be2[cc]) + __ldg(&proto[cc]);
        }
    }
}

// ============================================================
extern "C" void kernel_launch(void* const* d_in, const int* in_sizes, int n_in,
                              void* d_out, int out_size) {
    const float* query     = (const float*)d_in[0];
    const float* cand_text = (const float*)d_in[1];
    const float* cand_img  = (const float*)d_in[2];
    const float* proto     = (const float*)d_in[3];
    const float* W_txt  = (const float*)d_in[4];
    const float* b_txt  = (const float*)d_in[5];
    const float* g_txt  = (const float*)d_in[6];
    const float* be_txt = (const float*)d_in[7];
    const float* W_img  = (const float*)d_in[8];
    const float* b_img  = (const float*)d_in[9];
    const float* g_img  = (const float*)d_in[10];
    const float* be_img = (const float*)d_in[11];
    const float* Wq = (const float*)d_in[12];
    const float* bq = (const float*)d_in[13];
    const float* Wk = (const float*)d_in[14];
    const float* bk = (const float*)d_in[15];
    const float* Wv = (const float*)d_in[16];
    const float* bv = (const float*)d_in[17];
    const float* Wo = (const float*)d_in[18];
    const float* bo = (const float*)d_in[19];
    const float* g1  = (const float*)d_in[20];
    const float* be1 = (const float*)d_in[21];
    const float* W1 = (const float*)d_in[22];
    const float* b1 = (const float*)d_in[23];
    const float* W2 = (const float*)d_in[24];
    const float* b2 = (const float*)d_in[25];
    const float* g2  = (const float*)d_in[26];
    const float* be2 = (const float*)d_in[27];
    float* out = (float*)d_out;

    sim_kernel<<<SIM_BLOCKS, 1024>>>(query, cand_text);
    tail_kernel<<<TB, 1024>>>(query, cand_text, cand_img, proto,
                              W_txt, b_txt, g_txt, be_txt,
                              W_img, b_img, g_img, be_img,
                              Wq, bq, Wk, bk, Wv, bv, Wo, bo,
                              g1, be1, W1, b1, W2, b2, g2, be2, out);
}